// round 8
// baseline (speedup 1.0000x reference)
#include <cuda_runtime.h>
#include <math.h>

// Problem constants
#define NB 4          // batch
#define CC 512        // channels C
#define KPD 512       // key planes
#define NP 4096       // H*W
#define MP 4096       // HS*WS

// ----------------------------------------------------------------------------
// Device-global scratch (alloc-free per harness rules)
// ----------------------------------------------------------------------------
__device__ float g_F[(size_t)NB * NP * KPD];   // [b, n, k]   32 MB
__device__ float g_G[(size_t)NB * MP * KPD];   // [b, m, k]   32 MB
__device__ float g_H[(size_t)NB * MP * CC];    // [b, m, c]   32 MB
__device__ float g_S[(size_t)NB * NP * MP];    // [b, n, m]  256 MB

// ----------------------------------------------------------------------------
// Kernel 1: 1x1 conv as GEMM.
//   Out[b, i, j] = sum_k X[b, k, i] * W[j, k] + bias[j]
// X: [B, K, I] (channel-major, pixels contiguous), W: [J, K] row-major.
// I = 4096, K = 512, J = 512. Tile 128x128x8, 256 threads, 8x8 micro.
// dest: 0 -> g_F, 1 -> g_G, 2 -> g_H
// ----------------------------------------------------------------------------
__global__ void __launch_bounds__(256)
conv1x1_gemm(const float* __restrict__ X, const float* __restrict__ W,
             const float* __restrict__ bias, int dest)
{
    const int I = NP, K = KPD, J = KPD;
    __shared__ float As[8][128];
    __shared__ float Bs[8][129];

    int b  = blockIdx.z;
    int i0 = blockIdx.x * 128;
    int j0 = blockIdx.y * 128;
    const float* Xb = X + (size_t)b * K * I;
    float* Out = (dest == 0) ? g_F : (dest == 1) ? g_G : g_H;
    float* Outb = Out + (size_t)b * I * J;

    int tid = threadIdx.x;
    int tx = tid & 15, ty = tid >> 4;

    float acc[8][8];
#pragma unroll
    for (int ii = 0; ii < 8; ii++)
#pragma unroll
        for (int jj = 0; jj < 8; jj++) acc[ii][jj] = 0.f;

    for (int kk = 0; kk < K; kk += 8) {
        // A tile: As[k][i] = X[b, kk+k, i0+i]  (coalesced over i)
#pragma unroll
        for (int p = 0; p < 4; p++) {
            int e = tid + p * 256;
            int i = e & 127, k = e >> 7;
            As[k][i] = Xb[(size_t)(kk + k) * I + i0 + i];
        }
        // B tile: Bs[k][j] = W[(j0+j)*K + kk + k] (W is tiny, L2-resident)
#pragma unroll
        for (int p = 0; p < 4; p++) {
            int e = tid + p * 256;
            int k = e & 7, j = e >> 3;
            Bs[k][j] = W[(size_t)(j0 + j) * K + kk + k];
        }
        __syncthreads();
#pragma unroll
        for (int k = 0; k < 8; k++) {
            float a[8], bb[8];
#pragma unroll
            for (int ii = 0; ii < 8; ii++) a[ii] = As[k][ty + ii * 16];
#pragma unroll
            for (int jj = 0; jj < 8; jj++) bb[jj] = Bs[k][tx + jj * 16];
#pragma unroll
            for (int ii = 0; ii < 8; ii++)
#pragma unroll
                for (int jj = 0; jj < 8; jj++)
                    acc[ii][jj] += a[ii] * bb[jj];
        }
        __syncthreads();
    }

#pragma unroll
    for (int jj = 0; jj < 8; jj++) {
        float bv = bias[j0 + tx + jj * 16];
#pragma unroll
        for (int ii = 0; ii < 8; ii++) {
            Outb[(size_t)(i0 + ty + ii * 16) * J + (j0 + tx + jj * 16)] =
                acc[ii][jj] + bv;
        }
    }
}

// ----------------------------------------------------------------------------
// Kernel 2: attention logits, NT GEMM.
//   L[b, n, m] = sum_k F[b, n, k] * G[b, m, k]
// Tile 128x128x8.
// ----------------------------------------------------------------------------
__global__ void __launch_bounds__(256)
logits_gemm()
{
    __shared__ float As[8][129];
    __shared__ float Bs[8][129];

    int b  = blockIdx.z;
    int n0 = blockIdx.x * 128;
    int m0 = blockIdx.y * 128;
    const float* Fb = g_F + (size_t)b * NP * KPD;
    const float* Gb = g_G + (size_t)b * MP * KPD;
    float* Sb = g_S + (size_t)b * NP * MP;

    int tid = threadIdx.x;
    int tx = tid & 15, ty = tid >> 4;

    float acc[8][8];
#pragma unroll
    for (int ii = 0; ii < 8; ii++)
#pragma unroll
        for (int jj = 0; jj < 8; jj++) acc[ii][jj] = 0.f;

    for (int kk = 0; kk < KPD; kk += 8) {
        // As[k][i] = F[(n0+i)*KPD + kk+k]; 8-wide (32B) contiguous reads
#pragma unroll
        for (int p = 0; p < 4; p++) {
            int e = tid + p * 256;
            int k = e & 7, i = e >> 3;
            As[k][i] = Fb[(size_t)(n0 + i) * KPD + kk + k];
        }
#pragma unroll
        for (int p = 0; p < 4; p++) {
            int e = tid + p * 256;
            int k = e & 7, j = e >> 3;
            Bs[k][j] = Gb[(size_t)(m0 + j) * KPD + kk + k];
        }
        __syncthreads();
#pragma unroll
        for (int k = 0; k < 8; k++) {
            float a[8], bb[8];
#pragma unroll
            for (int ii = 0; ii < 8; ii++) a[ii] = As[k][ty + ii * 16];
#pragma unroll
            for (int jj = 0; jj < 8; jj++) bb[jj] = Bs[k][tx + jj * 16];
#pragma unroll
            for (int ii = 0; ii < 8; ii++)
#pragma unroll
                for (int jj = 0; jj < 8; jj++)
                    acc[ii][jj] += a[ii] * bb[jj];
        }
        __syncthreads();
    }

#pragma unroll
    for (int ii = 0; ii < 8; ii++)
#pragma unroll
        for (int jj = 0; jj < 8; jj++) {
            Sb[(size_t)(n0 + ty + ii * 16) * MP + (m0 + tx + jj * 16)] =
                acc[ii][jj];
        }
}

// ----------------------------------------------------------------------------
// Kernel 3: row softmax over M, in place in g_S. One block (256 threads) per
// row; 16 elements per thread held in registers.
// ----------------------------------------------------------------------------
__global__ void __launch_bounds__(256)
softmax_rows()
{
    __shared__ float red[256];
    int row = blockIdx.x;                // in [0, NB*NP)
    size_t base = (size_t)row * MP;
    int tid = threadIdx.x;

    float v[16];
    float lmax = -1e30f;
#pragma unroll
    for (int t = 0; t < 16; t++) {
        v[t] = g_S[base + tid + t * 256];
        lmax = fmaxf(lmax, v[t]);
    }
    red[tid] = lmax;
    __syncthreads();
    for (int s = 128; s > 0; s >>= 1) {
        if (tid < s) red[tid] = fmaxf(red[tid], red[tid + s]);
        __syncthreads();
    }
    float m = red[0];
    __syncthreads();

    float lsum = 0.f;
#pragma unroll
    for (int t = 0; t < 16; t++) {
        v[t] = __expf(v[t] - m);
        lsum += v[t];
    }
    red[tid] = lsum;
    __syncthreads();
    for (int s = 128; s > 0; s >>= 1) {
        if (tid < s) red[tid] += red[tid + s];
        __syncthreads();
    }
    float inv = 1.f / red[0];

#pragma unroll
    for (int t = 0; t < 16; t++)
        g_S[base + tid + t * 256] = v[t] * inv;
}

// ----------------------------------------------------------------------------
// Kernel 4: dual NN GEMM + fused epilogue.
//   mean[n,c] = sum_m S[n,m] * H[m,c]
//   e2[n,c]   = sum_m S[n,m] * H[m,c]^2
//   out[b,c,n] = sqrt(relu(e2 - mean^2)) * c_x[b,c,n] + mean
// Tile 128(n) x 64(c) x 8(m), 256 threads, 8x4 dual micro-tile.
// ----------------------------------------------------------------------------
__global__ void __launch_bounds__(256)
meanstd_gemm(const float* __restrict__ c_x, float* __restrict__ out)
{
    __shared__ float As[8][129];   // S tile
    __shared__ float Bs[8][64];    // H tile

    int b  = blockIdx.z;
    int n0 = blockIdx.x * 128;
    int c0 = blockIdx.y * 64;
    const float* Sb = g_S + (size_t)b * NP * MP;
    const float* Hb = g_H + (size_t)b * MP * CC;

    int tid = threadIdx.x;
    int tx = tid & 15, ty = tid >> 4;

    float am[8][4], ae[8][4];
#pragma unroll
    for (int ii = 0; ii < 8; ii++)
#pragma unroll
        for (int jj = 0; jj < 4; jj++) { am[ii][jj] = 0.f; ae[ii][jj] = 0.f; }

    for (int mm = 0; mm < MP; mm += 8) {
        // S tile: As[k][i] = S[(n0+i)*MP + mm+k]; contiguous 8-wide over k
#pragma unroll
        for (int p = 0; p < 4; p++) {
            int e = tid + p * 256;
            int k = e & 7, i = e >> 3;
            As[k][i] = Sb[(size_t)(n0 + i) * MP + mm + k];
        }
        // H tile: Bs[k][j] = H[(mm+k)*CC + c0+j]; 64-wide coalesced
#pragma unroll
        for (int p = 0; p < 2; p++) {
            int e = tid + p * 256;
            int j = e & 63, k = e >> 6;
            Bs[k][j] = Hb[(size_t)(mm + k) * CC + c0 + j];
        }
        __syncthreads();
#pragma unroll
        for (int k = 0; k < 8; k++) {
            float a[8], bb[4], b2[4];
#pragma unroll
            for (int ii = 0; ii < 8; ii++) a[ii] = As[k][ty + ii * 16];
#pragma unroll
            for (int jj = 0; jj < 4; jj++) {
                bb[jj] = Bs[k][tx + jj * 16];
                b2[jj] = bb[jj] * bb[jj];
            }
#pragma unroll
            for (int ii = 0; ii < 8; ii++)
#pragma unroll
                for (int jj = 0; jj < 4; jj++) {
                    am[ii][jj] += a[ii] * bb[jj];
                    ae[ii][jj] += a[ii] * b2[jj];
                }
        }
        __syncthreads();
    }

    // Epilogue: std*c_x + mean, written in [b, c, n] layout.
#pragma unroll
    for (int ii = 0; ii < 8; ii++) {
        int n = n0 + ty + ii * 16;
#pragma unroll
        for (int jj = 0; jj < 4; jj++) {
            int c = c0 + tx + jj * 16;
            float mval = am[ii][jj];
            float e2   = ae[ii][jj];
            float sd   = sqrtf(fmaxf(e2 - mval * mval, 0.f));
            size_t idx = ((size_t)b * CC + c) * NP + n;
            out[idx] = sd * c_x[idx] + mval;
        }
    }
}

// ----------------------------------------------------------------------------
// Launch
// ----------------------------------------------------------------------------
extern "C" void kernel_launch(void* const* d_in, const int* in_sizes, int n_in,
                              void* d_out, int out_size)
{
    const float* c_x  = (const float*)d_in[0];
    const float* s_x  = (const float*)d_in[1];
    const float* c_1x = (const float*)d_in[2];
    const float* s_1x = (const float*)d_in[3];
    const float* f_w  = (const float*)d_in[4];
    const float* f_b  = (const float*)d_in[5];
    const float* g_w  = (const float*)d_in[6];
    const float* g_b  = (const float*)d_in[7];
    const float* h_w  = (const float*)d_in[8];
    const float* h_b  = (const float*)d_in[9];
    float* out = (float*)d_out;

    (void)in_sizes; (void)n_in; (void)out_size;

    dim3 gridA(NP / 128, KPD / 128, NB);           // (32, 4, 4)
    conv1x1_gemm<<<gridA, 256>>>(c_1x, f_w, f_b, 0);   // F
    conv1x1_gemm<<<gridA, 256>>>(s_1x, g_w, g_b, 1);   // G
    conv1x1_gemm<<<gridA, 256>>>(s_x,  h_w, h_b, 2);   // Hs

    dim3 gridL(NP / 128, MP / 128, NB);            // (32, 32, 4)
    logits_gemm<<<gridL, 256>>>();

    softmax_rows<<<NB * NP, 256>>>();              // 16384 rows

    dim3 gridM(NP / 128, CC / 64, NB);             // (32, 8, 4)
    meanstd_gemm<<<gridM, 256>>>(c_x, out);
}

// round 9
// speedup vs baseline: 1.0015x; 1.0015x over previous
#include <cuda_runtime.h>
#include <math.h>

// Problem constants
#define NB 4          // batch
#define CC 512        // channels C
#define KPD 512       // key planes
#define NP 4096       // H*W
#define MP 4096       // HS*WS

// ----------------------------------------------------------------------------
// Device-global scratch (alloc-free per harness rules)
// ----------------------------------------------------------------------------
__device__ float g_F[(size_t)NB * NP * KPD];   // [b, n, k]   32 MB
__device__ float g_G[(size_t)NB * MP * KPD];   // [b, m, k]   32 MB
__device__ float g_H[(size_t)NB * MP * CC];    // [b, m, c]   32 MB
__device__ float g_S[(size_t)NB * NP * MP];    // [b, n, m]  256 MB

// ----------------------------------------------------------------------------
// Kernel 1: 1x1 conv as GEMM.
//   Out[b, i, j] = sum_k X[b, k, i] * W[j, k] + bias[j]
// X: [B, K, I] (channel-major, pixels contiguous), W: [J, K] row-major.
// I = 4096, K = 512, J = 512. Tile 128x128x8, 256 threads, 8x8 micro.
// dest: 0 -> g_F, 1 -> g_G, 2 -> g_H
// ----------------------------------------------------------------------------
__global__ void __launch_bounds__(256)
conv1x1_gemm(const float* __restrict__ X, const float* __restrict__ W,
             const float* __restrict__ bias, int dest)
{
    const int I = NP, K = KPD, J = KPD;
    __shared__ float As[8][128];
    __shared__ float Bs[8][129];

    int b  = blockIdx.z;
    int i0 = blockIdx.x * 128;
    int j0 = blockIdx.y * 128;
    const float* Xb = X + (size_t)b * K * I;
    float* Out = (dest == 0) ? g_F : (dest == 1) ? g_G : g_H;
    float* Outb = Out + (size_t)b * I * J;

    int tid = threadIdx.x;
    int tx = tid & 15, ty = tid >> 4;

    float acc[8][8];
#pragma unroll
    for (int ii = 0; ii < 8; ii++)
#pragma unroll
        for (int jj = 0; jj < 8; jj++) acc[ii][jj] = 0.f;

    for (int kk = 0; kk < K; kk += 8) {
        // A tile: As[k][i] = X[b, kk+k, i0+i]  (coalesced over i)
#pragma unroll
        for (int p = 0; p < 4; p++) {
            int e = tid + p * 256;
            int i = e & 127, k = e >> 7;
            As[k][i] = Xb[(size_t)(kk + k) * I + i0 + i];
        }
        // B tile: Bs[k][j] = W[(j0+j)*K + kk + k] (W is tiny, L2-resident)
#pragma unroll
        for (int p = 0; p < 4; p++) {
            int e = tid + p * 256;
            int k = e & 7, j = e >> 3;
            Bs[k][j] = W[(size_t)(j0 + j) * K + kk + k];
        }
        __syncthreads();
#pragma unroll
        for (int k = 0; k < 8; k++) {
            float a[8], bb[8];
#pragma unroll
            for (int ii = 0; ii < 8; ii++) a[ii] = As[k][ty + ii * 16];
#pragma unroll
            for (int jj = 0; jj < 8; jj++) bb[jj] = Bs[k][tx + jj * 16];
#pragma unroll
            for (int ii = 0; ii < 8; ii++)
#pragma unroll
                for (int jj = 0; jj < 8; jj++)
                    acc[ii][jj] += a[ii] * bb[jj];
        }
        __syncthreads();
    }

#pragma unroll
    for (int jj = 0; jj < 8; jj++) {
        float bv = bias[j0 + tx + jj * 16];
#pragma unroll
        for (int ii = 0; ii < 8; ii++) {
            Outb[(size_t)(i0 + ty + ii * 16) * J + (j0 + tx + jj * 16)] =
                acc[ii][jj] + bv;
        }
    }
}

// ----------------------------------------------------------------------------
// Kernel 2: attention logits, NT GEMM.
//   L[b, n, m] = sum_k F[b, n, k] * G[b, m, k]
// Tile 128x128x8.
// ----------------------------------------------------------------------------
__global__ void __launch_bounds__(256)
logits_gemm()
{
    __shared__ float As[8][129];
    __shared__ float Bs[8][129];

    int b  = blockIdx.z;
    int n0 = blockIdx.x * 128;
    int m0 = blockIdx.y * 128;
    const float* Fb = g_F + (size_t)b * NP * KPD;
    const float* Gb = g_G + (size_t)b * MP * KPD;
    float* Sb = g_S + (size_t)b * NP * MP;

    int tid = threadIdx.x;
    int tx = tid & 15, ty = tid >> 4;

    float acc[8][8];
#pragma unroll
    for (int ii = 0; ii < 8; ii++)
#pragma unroll
        for (int jj = 0; jj < 8; jj++) acc[ii][jj] = 0.f;

    for (int kk = 0; kk < KPD; kk += 8) {
        // As[k][i] = F[(n0+i)*KPD + kk+k]; 8-wide (32B) contiguous reads
#pragma unroll
        for (int p = 0; p < 4; p++) {
            int e = tid + p * 256;
            int k = e & 7, i = e >> 3;
            As[k][i] = Fb[(size_t)(n0 + i) * KPD + kk + k];
        }
#pragma unroll
        for (int p = 0; p < 4; p++) {
            int e = tid + p * 256;
            int k = e & 7, j = e >> 3;
            Bs[k][j] = Gb[(size_t)(m0 + j) * KPD + kk + k];
        }
        __syncthreads();
#pragma unroll
        for (int k = 0; k < 8; k++) {
            float a[8], bb[8];
#pragma unroll
            for (int ii = 0; ii < 8; ii++) a[ii] = As[k][ty + ii * 16];
#pragma unroll
            for (int jj = 0; jj < 8; jj++) bb[jj] = Bs[k][tx + jj * 16];
#pragma unroll
            for (int ii = 0; ii < 8; ii++)
#pragma unroll
                for (int jj = 0; jj < 8; jj++)
                    acc[ii][jj] += a[ii] * bb[jj];
        }
        __syncthreads();
    }

#pragma unroll
    for (int ii = 0; ii < 8; ii++)
#pragma unroll
        for (int jj = 0; jj < 8; jj++) {
            Sb[(size_t)(n0 + ty + ii * 16) * MP + (m0 + tx + jj * 16)] =
                acc[ii][jj];
        }
}

// ----------------------------------------------------------------------------
// Kernel 3: row softmax over M, in place in g_S. One block (256 threads) per
// row; 16 elements per thread held in registers.
// ----------------------------------------------------------------------------
__global__ void __launch_bounds__(256)
softmax_rows()
{
    __shared__ float red[256];
    int row = blockIdx.x;                // in [0, NB*NP)
    size_t base = (size_t)row * MP;
    int tid = threadIdx.x;

    float v[16];
    float lmax = -1e30f;
#pragma unroll
    for (int t = 0; t < 16; t++) {
        v[t] = g_S[base + tid + t * 256];
        lmax = fmaxf(lmax, v[t]);
    }
    red[tid] = lmax;
    __syncthreads();
    for (int s = 128; s > 0; s >>= 1) {
        if (tid < s) red[tid] = fmaxf(red[tid], red[tid + s]);
        __syncthreads();
    }
    float m = red[0];
    __syncthreads();

    float lsum = 0.f;
#pragma unroll
    for (int t = 0; t < 16; t++) {
        v[t] = __expf(v[t] - m);
        lsum += v[t];
    }
    red[tid] = lsum;
    __syncthreads();
    for (int s = 128; s > 0; s >>= 1) {
        if (tid < s) red[tid] += red[tid + s];
        __syncthreads();
    }
    float inv = 1.f / red[0];

#pragma unroll
    for (int t = 0; t < 16; t++)
        g_S[base + tid + t * 256] = v[t] * inv;
}

// ----------------------------------------------------------------------------
// Kernel 4: dual NN GEMM + fused epilogue.
//   mean[n,c] = sum_m S[n,m] * H[m,c]
//   e2[n,c]   = sum_m S[n,m] * H[m,c]^2
//   out[b,c,n] = sqrt(relu(e2 - mean^2)) * c_x[b,c,n] + mean
// Tile 128(n) x 64(c) x 8(m), 256 threads, 8x4 dual micro-tile.
// ----------------------------------------------------------------------------
__global__ void __launch_bounds__(256)
meanstd_gemm(const float* __restrict__ c_x, float* __restrict__ out)
{
    __shared__ float As[8][129];   // S tile
    __shared__ float Bs[8][64];    // H tile

    int b  = blockIdx.z;
    int n0 = blockIdx.x * 128;
    int c0 = blockIdx.y * 64;
    const float* Sb = g_S + (size_t)b * NP * MP;
    const float* Hb = g_H + (size_t)b * MP * CC;

    int tid = threadIdx.x;
    int tx = tid & 15, ty = tid >> 4;

    float am[8][4], ae[8][4];
#pragma unroll
    for (int ii = 0; ii < 8; ii++)
#pragma unroll
        for (int jj = 0; jj < 4; jj++) { am[ii][jj] = 0.f; ae[ii][jj] = 0.f; }

    for (int mm = 0; mm < MP; mm += 8) {
        // S tile: As[k][i] = S[(n0+i)*MP + mm+k]; contiguous 8-wide over k
#pragma unroll
        for (int p = 0; p < 4; p++) {
            int e = tid + p * 256;
            int k = e & 7, i = e >> 3;
            As[k][i] = Sb[(size_t)(n0 + i) * MP + mm + k];
        }
        // H tile: Bs[k][j] = H[(mm+k)*CC + c0+j]; 64-wide coalesced
#pragma unroll
        for (int p = 0; p < 2; p++) {
            int e = tid + p * 256;
            int j = e & 63, k = e >> 6;
            Bs[k][j] = Hb[(size_t)(mm + k) * CC + c0 + j];
        }
        __syncthreads();
#pragma unroll
        for (int k = 0; k < 8; k++) {
            float a[8], bb[4], b2[4];
#pragma unroll
            for (int ii = 0; ii < 8; ii++) a[ii] = As[k][ty + ii * 16];
#pragma unroll
            for (int jj = 0; jj < 4; jj++) {
                bb[jj] = Bs[k][tx + jj * 16];
                b2[jj] = bb[jj] * bb[jj];
            }
#pragma unroll
            for (int ii = 0; ii < 8; ii++)
#pragma unroll
                for (int jj = 0; jj < 4; jj++) {
                    am[ii][jj] += a[ii] * bb[jj];
                    ae[ii][jj] += a[ii] * b2[jj];
                }
        }
        __syncthreads();
    }

    // Epilogue: std*c_x + mean, written in [b, c, n] layout.
#pragma unroll
    for (int ii = 0; ii < 8; ii++) {
        int n = n0 + ty + ii * 16;
#pragma unroll
        for (int jj = 0; jj < 4; jj++) {
            int c = c0 + tx + jj * 16;
            float mval = am[ii][jj];
            float e2   = ae[ii][jj];
            float sd   = sqrtf(fmaxf(e2 - mval * mval, 0.f));
            size_t idx = ((size_t)b * CC + c) * NP + n;
            out[idx] = sd * c_x[idx] + mval;
        }
    }
}

// ----------------------------------------------------------------------------
// Launch
// ----------------------------------------------------------------------------
extern "C" void kernel_launch(void* const* d_in, const int* in_sizes, int n_in,
                              void* d_out, int out_size)
{
    const float* c_x  = (const float*)d_in[0];
    const float* s_x  = (const float*)d_in[1];
    const float* c_1x = (const float*)d_in[2];
    const float* s_1x = (const float*)d_in[3];
    const float* f_w  = (const float*)d_in[4];
    const float* f_b  = (const float*)d_in[5];
    const float* g_w  = (const float*)d_in[6];
    const float* g_b  = (const float*)d_in[7];
    const float* h_w  = (const float*)d_in[8];
    const float* h_b  = (const float*)d_in[9];
    float* out = (float*)d_out;

    (void)in_sizes; (void)n_in; (void)out_size;

    dim3 gridA(NP / 128, KPD / 128, NB);           // (32, 4, 4)
    conv1x1_gemm<<<gridA, 256>>>(c_1x, f_w, f_b, 0);   // F
    conv1x1_gemm<<<gridA, 256>>>(s_1x, g_w, g_b, 1);   // G
    conv1x1_gemm<<<gridA, 256>>>(s_x,  h_w, h_b, 2);   // Hs

    dim3 gridL(NP / 128, MP / 128, NB);            // (32, 32, 4)
    logits_gemm<<<gridL, 256>>>();

    softmax_rows<<<NB * NP, 256>>>();              // 16384 rows

    dim3 gridM(NP / 128, CC / 64, NB);             // (32, 8, 4)
    meanstd_gemm<<<gridM, 256>>>(c_x, out);
}

// round 10
// speedup vs baseline: 1.2263x; 1.2244x over previous
#include <cuda_runtime.h>
#include <math.h>

// Problem constants
#define NB 4          // batch
#define CC 512        // channels C
#define KPD 512       // key planes
#define NP 4096       // H*W
#define MP 4096       // HS*WS

// ----------------------------------------------------------------------------
// Packed f32x2 helpers (Blackwell sm_103a): 2 fp32 FMAs per fma-pipe issue.
// ----------------------------------------------------------------------------
typedef unsigned long long u64;

__device__ __forceinline__ void ffma2(u64& d, u64 a, u64 b) {
    asm("fma.rn.f32x2 %0, %1, %2, %0;" : "+l"(d) : "l"(a), "l"(b));
}
__device__ __forceinline__ u64 mul2(u64 a, u64 b) {
    u64 r; asm("mul.rn.f32x2 %0, %1, %2;" : "=l"(r) : "l"(a), "l"(b)); return r;
}
__device__ __forceinline__ u64 dup2(float x) {
    u64 r; asm("mov.b64 %0, {%1, %1};" : "=l"(r) : "f"(x)); return r;
}
__device__ __forceinline__ float2 unpack2(u64 v) {
    float2 f; asm("mov.b64 {%0, %1}, %2;" : "=f"(f.x), "=f"(f.y) : "l"(v)); return f;
}
__device__ __forceinline__ u64 ldp(const float* p) {   // 8B-aligned pair load
    return *reinterpret_cast<const u64*>(p);
}

// ----------------------------------------------------------------------------
// Device-global scratch (alloc-free per harness rules)
// ----------------------------------------------------------------------------
__device__ float g_F[(size_t)NB * NP * KPD];   // [b, n, k]   32 MB
__device__ float g_G[(size_t)NB * MP * KPD];   // [b, m, k]   32 MB
__device__ float g_H[(size_t)NB * MP * CC];    // [b, m, c]   32 MB
__device__ float g_S[(size_t)NB * NP * MP];    // [b, n, m]  256 MB

// ----------------------------------------------------------------------------
// Kernel 1: 1x1 conv as GEMM (packed f32x2).
//   Out[b, i, j] = sum_k X[b, k, i] * W[j, k] + bias[j]
// Tile 128x128x8, 256 threads. Per thread: 8 rows (4 adjacent pairs) x
// 8 cols (4 adjacent pairs). Rows: 2*ty+32*ii(+0/1), cols: 2*tx+32*jj(+0/1).
// ----------------------------------------------------------------------------
__global__ void __launch_bounds__(256)
conv1x1_gemm(const float* __restrict__ X, const float* __restrict__ W,
             const float* __restrict__ bias, int dest)
{
    const int I = NP, K = KPD, J = KPD;
    __shared__ __align__(16) float As[8 * 128];   // writes coalesced over i
    __shared__ __align__(16) float Bs[8 * 130];   // strided-k writes: pad 2

    int b  = blockIdx.z;
    int i0 = blockIdx.x * 128;
    int j0 = blockIdx.y * 128;
    const float* Xb = X + (size_t)b * K * I;
    float* Out = (dest == 0) ? g_F : (dest == 1) ? g_G : g_H;
    float* Outb = Out + (size_t)b * I * J;

    int tid = threadIdx.x;
    int tx = tid & 15, ty = tid >> 4;

    u64 acc[8][4];
#pragma unroll
    for (int r = 0; r < 8; r++)
#pragma unroll
        for (int j = 0; j < 4; j++) acc[r][j] = 0ull;

    for (int kk = 0; kk < K; kk += 8) {
        // A tile: As[k][i] = X[b, kk+k, i0+i]  (coalesced over i)
#pragma unroll
        for (int p = 0; p < 4; p++) {
            int e = tid + p * 256;
            int i = e & 127, k = e >> 7;
            As[k * 128 + i] = Xb[(size_t)(kk + k) * I + i0 + i];
        }
        // B tile: Bs[k][j] = W[(j0+j)*K + kk + k]
#pragma unroll
        for (int p = 0; p < 4; p++) {
            int e = tid + p * 256;
            int k = e & 7, j = e >> 3;
            Bs[k * 130 + j] = W[(size_t)(j0 + j) * K + kk + k];
        }
        __syncthreads();
#pragma unroll
        for (int k = 0; k < 8; k++) {
            u64 ad[8], bp[4];
#pragma unroll
            for (int ii = 0; ii < 4; ii++) {
                float2 a = unpack2(ldp(&As[k * 128 + 2 * ty + 32 * ii]));
                ad[2 * ii]     = dup2(a.x);
                ad[2 * ii + 1] = dup2(a.y);
            }
#pragma unroll
            for (int jj = 0; jj < 4; jj++)
                bp[jj] = ldp(&Bs[k * 130 + 2 * tx + 32 * jj]);
#pragma unroll
            for (int r = 0; r < 8; r++)
#pragma unroll
                for (int jj = 0; jj < 4; jj++)
                    ffma2(acc[r][jj], ad[r], bp[jj]);
        }
        __syncthreads();
    }

#pragma unroll
    for (int r = 0; r < 8; r++) {
        int i = i0 + 2 * ty + 32 * (r >> 1) + (r & 1);
#pragma unroll
        for (int jj = 0; jj < 4; jj++) {
            int j = j0 + 2 * tx + 32 * jj;
            float2 v = unpack2(acc[r][jj]);
            float2 bv = *reinterpret_cast<const float2*>(&bias[j]);
            v.x += bv.x; v.y += bv.y;
            *reinterpret_cast<float2*>(&Outb[(size_t)i * J + j]) = v;
        }
    }
}

// ----------------------------------------------------------------------------
// Kernel 2: attention logits, NT GEMM (packed f32x2).
//   L[b, n, m] = sum_k F[b, n, k] * G[b, m, k]
// ----------------------------------------------------------------------------
__global__ void __launch_bounds__(256)
logits_gemm()
{
    __shared__ __align__(16) float As[8 * 130];   // strided-k writes
    __shared__ __align__(16) float Bs[8 * 130];

    int b  = blockIdx.z;
    int n0 = blockIdx.x * 128;
    int m0 = blockIdx.y * 128;
    const float* Fb = g_F + (size_t)b * NP * KPD;
    const float* Gb = g_G + (size_t)b * MP * KPD;
    float* Sb = g_S + (size_t)b * NP * MP;

    int tid = threadIdx.x;
    int tx = tid & 15, ty = tid >> 4;

    u64 acc[8][4];
#pragma unroll
    for (int r = 0; r < 8; r++)
#pragma unroll
        for (int j = 0; j < 4; j++) acc[r][j] = 0ull;

    for (int kk = 0; kk < KPD; kk += 8) {
#pragma unroll
        for (int p = 0; p < 4; p++) {
            int e = tid + p * 256;
            int k = e & 7, i = e >> 3;
            As[k * 130 + i] = Fb[(size_t)(n0 + i) * KPD + kk + k];
        }
#pragma unroll
        for (int p = 0; p < 4; p++) {
            int e = tid + p * 256;
            int k = e & 7, j = e >> 3;
            Bs[k * 130 + j] = Gb[(size_t)(m0 + j) * KPD + kk + k];
        }
        __syncthreads();
#pragma unroll
        for (int k = 0; k < 8; k++) {
            u64 ad[8], bp[4];
#pragma unroll
            for (int ii = 0; ii < 4; ii++) {
                float2 a = unpack2(ldp(&As[k * 130 + 2 * ty + 32 * ii]));
                ad[2 * ii]     = dup2(a.x);
                ad[2 * ii + 1] = dup2(a.y);
            }
#pragma unroll
            for (int jj = 0; jj < 4; jj++)
                bp[jj] = ldp(&Bs[k * 130 + 2 * tx + 32 * jj]);
#pragma unroll
            for (int r = 0; r < 8; r++)
#pragma unroll
                for (int jj = 0; jj < 4; jj++)
                    ffma2(acc[r][jj], ad[r], bp[jj]);
        }
        __syncthreads();
    }

#pragma unroll
    for (int r = 0; r < 8; r++) {
        int n = n0 + 2 * ty + 32 * (r >> 1) + (r & 1);
#pragma unroll
        for (int jj = 0; jj < 4; jj++) {
            int m = m0 + 2 * tx + 32 * jj;
            float2 v = unpack2(acc[r][jj]);
            *reinterpret_cast<float2*>(&Sb[(size_t)n * MP + m]) = v;
        }
    }
}

// ----------------------------------------------------------------------------
// Kernel 3: row softmax over M, in place in g_S.
// ----------------------------------------------------------------------------
__global__ void __launch_bounds__(256)
softmax_rows()
{
    __shared__ float red[256];
    int row = blockIdx.x;                // in [0, NB*NP)
    size_t base = (size_t)row * MP;
    int tid = threadIdx.x;

    float v[16];
    float lmax = -1e30f;
#pragma unroll
    for (int t = 0; t < 16; t++) {
        v[t] = g_S[base + tid + t * 256];
        lmax = fmaxf(lmax, v[t]);
    }
    red[tid] = lmax;
    __syncthreads();
    for (int s = 128; s > 0; s >>= 1) {
        if (tid < s) red[tid] = fmaxf(red[tid], red[tid + s]);
        __syncthreads();
    }
    float m = red[0];
    __syncthreads();

    float lsum = 0.f;
#pragma unroll
    for (int t = 0; t < 16; t++) {
        v[t] = __expf(v[t] - m);
        lsum += v[t];
    }
    red[tid] = lsum;
    __syncthreads();
    for (int s = 128; s > 0; s >>= 1) {
        if (tid < s) red[tid] += red[tid + s];
        __syncthreads();
    }
    float inv = 1.f / red[0];

#pragma unroll
    for (int t = 0; t < 16; t++)
        g_S[base + tid + t * 256] = v[t] * inv;
}

// ----------------------------------------------------------------------------
// Kernel 4: dual NN GEMM + fused epilogue (packed f32x2).
//   mean[n,c] = sum_m S[n,m] * H[m,c]
//   e2[n,c]   = sum_m S[n,m] * H[m,c]^2
//   out[b,c,n] = sqrt(relu(e2 - mean^2)) * c_x[b,c,n] + mean
// Tile 128(n) x 64(c) x 8(m). Per thread 8 rows (pairs) x 4 cols (2 pairs),
// dual accumulators.
// ----------------------------------------------------------------------------
__global__ void __launch_bounds__(256)
meanstd_gemm(const float* __restrict__ c_x, float* __restrict__ out)
{
    __shared__ __align__(16) float As[8 * 130];   // S tile (strided-k writes)
    __shared__ __align__(16) float Bs[8 * 64];    // H tile (coalesced writes)

    int b  = blockIdx.z;
    int n0 = blockIdx.x * 128;
    int c0 = blockIdx.y * 64;
    const float* Sb = g_S + (size_t)b * NP * MP;
    const float* Hb = g_H + (size_t)b * MP * CC;

    int tid = threadIdx.x;
    int tx = tid & 15, ty = tid >> 4;

    u64 am[8][2], ae[8][2];
#pragma unroll
    for (int r = 0; r < 8; r++)
#pragma unroll
        for (int j = 0; j < 2; j++) { am[r][j] = 0ull; ae[r][j] = 0ull; }

    for (int mm = 0; mm < MP; mm += 8) {
        // S tile: As[k][i] = S[(n0+i)*MP + mm+k]
#pragma unroll
        for (int p = 0; p < 4; p++) {
            int e = tid + p * 256;
            int k = e & 7, i = e >> 3;
            As[k * 130 + i] = Sb[(size_t)(n0 + i) * MP + mm + k];
        }
        // H tile: Bs[k][j] = H[(mm+k)*CC + c0+j]
#pragma unroll
        for (int p = 0; p < 2; p++) {
            int e = tid + p * 256;
            int j = e & 63, k = e >> 6;
            Bs[k * 64 + j] = Hb[(size_t)(mm + k) * CC + c0 + j];
        }
        __syncthreads();
#pragma unroll
        for (int k = 0; k < 8; k++) {
            u64 ad[8], bp[2], b2[2];
#pragma unroll
            for (int ii = 0; ii < 4; ii++) {
                float2 a = unpack2(ldp(&As[k * 130 + 2 * ty + 32 * ii]));
                ad[2 * ii]     = dup2(a.x);
                ad[2 * ii + 1] = dup2(a.y);
            }
#pragma unroll
            for (int jj = 0; jj < 2; jj++) {
                bp[jj] = ldp(&Bs[k * 64 + 2 * tx + 32 * jj]);
                b2[jj] = mul2(bp[jj], bp[jj]);
            }
#pragma unroll
            for (int r = 0; r < 8; r++)
#pragma unroll
                for (int jj = 0; jj < 2; jj++) {
                    ffma2(am[r][jj], ad[r], bp[jj]);
                    ffma2(ae[r][jj], ad[r], b2[jj]);
                }
        }
        __syncthreads();
    }

    // Epilogue: std*c_x + mean, written in [b, c, n] layout.
#pragma unroll
    for (int r = 0; r < 8; r++) {
        int n = n0 + 2 * ty + 32 * (r >> 1) + (r & 1);
#pragma unroll
        for (int jj = 0; jj < 2; jj++) {
            int c = c0 + 2 * tx + 32 * jj;
            float2 mv = unpack2(am[r][jj]);
            float2 ev = unpack2(ae[r][jj]);

            float sd0 = sqrtf(fmaxf(ev.x - mv.x * mv.x, 0.f));
            float sd1 = sqrtf(fmaxf(ev.y - mv.y * mv.y, 0.f));

            size_t idx0 = ((size_t)b * CC + c)     * NP + n;
            size_t idx1 = ((size_t)b * CC + c + 1) * NP + n;
            out[idx0] = sd0 * c_x[idx0] + mv.x;
            out[idx1] = sd1 * c_x[idx1] + mv.y;
        }
    }
}

// ----------------------------------------------------------------------------
// Launch
// ----------------------------------------------------------------------------
extern "C" void kernel_launch(void* const* d_in, const int* in_sizes, int n_in,
                              void* d_out, int out_size)
{
    const float* c_x  = (const float*)d_in[0];
    const float* s_x  = (const float*)d_in[1];
    const float* c_1x = (const float*)d_in[2];
    const float* s_1x = (const float*)d_in[3];
    const float* f_w  = (const float*)d_in[4];
    const float* f_b  = (const float*)d_in[5];
    const float* g_w  = (const float*)d_in[6];
    const float* g_b  = (const float*)d_in[7];
    const float* h_w  = (const float*)d_in[8];
    const float* h_b  = (const float*)d_in[9];
    float* out = (float*)d_out;

    (void)in_sizes; (void)n_in; (void)out_size;

    dim3 gridA(NP / 128, KPD / 128, NB);           // (32, 4, 4)
    conv1x1_gemm<<<gridA, 256>>>(c_1x, f_w, f_b, 0);   // F
    conv1x1_gemm<<<gridA, 256>>>(s_1x, g_w, g_b, 1);   // G
    conv1x1_gemm<<<gridA, 256>>>(s_x,  h_w, h_b, 2);   // Hs

    dim3 gridL(NP / 128, MP / 128, NB);            // (32, 32, 4)
    logits_gemm<<<gridL, 256>>>();

    softmax_rows<<<NB * NP, 256>>>();              // 16384 rows

    dim3 gridM(NP / 128, CC / 64, NB);             // (32, 8, 4)
    meanstd_gemm<<<gridM, 256>>>(c_x, out);
}

// round 13
// speedup vs baseline: 2.5189x; 2.0541x over previous
#include <cuda_runtime.h>
#include <cuda_bf16.h>
#include <math.h>
#include <stdint.h>

// Problem constants
#define NB 4          // batch
#define CC 512        // channels C
#define KPD 512       // key planes
#define NP 4096       // H*W
#define MP 4096       // HS*WS

typedef unsigned long long u64;

// ============================================================================
// Packed f32x2 helpers (conv kernels)
// ============================================================================
__device__ __forceinline__ void ffma2(u64& d, u64 a, u64 b) {
    asm("fma.rn.f32x2 %0, %1, %2, %0;" : "+l"(d) : "l"(a), "l"(b));
}
__device__ __forceinline__ u64 dup2(float x) {
    u64 r; asm("mov.b64 %0, {%1, %1};" : "=l"(r) : "f"(x)); return r;
}
__device__ __forceinline__ float2 unpack2(u64 v) {
    float2 f; asm("mov.b64 {%0, %1}, %2;" : "=f"(f.x), "=f"(f.y) : "l"(v)); return f;
}
__device__ __forceinline__ u64 ldp(const float* p) {
    return *reinterpret_cast<const u64*>(p);
}

// ============================================================================
// bf16 split helpers
// ============================================================================
__device__ __forceinline__ uint32_t bpack2(float v0, float v1,
                                           uint32_t& lo_out) {
    __nv_bfloat16 h0 = __float2bfloat16(v0);
    __nv_bfloat16 h1 = __float2bfloat16(v1);
    __nv_bfloat16 l0 = __float2bfloat16(v0 - __bfloat162float(h0));
    __nv_bfloat16 l1 = __float2bfloat16(v1 - __bfloat162float(h1));
    uint16_t uh0 = *reinterpret_cast<uint16_t*>(&h0);
    uint16_t uh1 = *reinterpret_cast<uint16_t*>(&h1);
    uint16_t ul0 = *reinterpret_cast<uint16_t*>(&l0);
    uint16_t ul1 = *reinterpret_cast<uint16_t*>(&l1);
    lo_out = (uint32_t)ul0 | ((uint32_t)ul1 << 16);
    return (uint32_t)uh0 | ((uint32_t)uh1 << 16);
}

// ============================================================================
// HMMA / ldmatrix / cp.async (portable sm_80+ PTX — valid on plain sm_103)
// ============================================================================
__device__ __forceinline__ uint32_t smem_u32(const void* p) {
    uint32_t a;
    asm("{ .reg .u64 t; cvta.to.shared.u64 t, %1; cvt.u32.u64 %0, t; }"
        : "=r"(a) : "l"(p));
    return a;
}

#define LDM_X4(r0, r1, r2, r3, a) \
    asm volatile("ldmatrix.sync.aligned.m8n8.x4.shared.b16 {%0,%1,%2,%3}, [%4];" \
                 : "=r"(r0), "=r"(r1), "=r"(r2), "=r"(r3) : "r"(a))

__device__ __forceinline__ void mma16816(float* d, const uint32_t* a,
                                         uint32_t b0, uint32_t b1) {
    asm volatile(
        "mma.sync.aligned.m16n8k16.row.col.f32.bf16.bf16.f32 "
        "{%0,%1,%2,%3}, {%4,%5,%6,%7}, {%8,%9}, {%0,%1,%2,%3};"
        : "+f"(d[0]), "+f"(d[1]), "+f"(d[2]), "+f"(d[3])
        : "r"(a[0]), "r"(a[1]), "r"(a[2]), "r"(a[3]), "r"(b0), "r"(b1));
}

#define CP_ASYNC16(dst, src) \
    asm volatile("cp.async.cg.shared.global [%0], [%1], 16;" \
                 :: "r"(dst), "l"(src))
#define CP_COMMIT() asm volatile("cp.async.commit_group;" ::: "memory")
#define CP_WAIT0()  asm volatile("cp.async.wait_group 0;" ::: "memory")
#define CP_WAIT1()  asm volatile("cp.async.wait_group 1;" ::: "memory")

// ============================================================================
// Device-global scratch (alloc-free per harness rules)
// ============================================================================
__device__ float g_S[(size_t)NB * NP * MP];              // logits f32
__device__ __nv_bfloat16 g_Fh[(size_t)NB * NP * KPD];    // F [b][n][k] hi
__device__ __nv_bfloat16 g_Fl[(size_t)NB * NP * KPD];    // F lo
__device__ __nv_bfloat16 g_Gh[(size_t)NB * MP * KPD];    // G [b][m][k] hi
__device__ __nv_bfloat16 g_Gl[(size_t)NB * MP * KPD];
__device__ __nv_bfloat16 g_Hth[(size_t)NB * CC * MP];    // Ht [b][c][m]
__device__ __nv_bfloat16 g_Htl[(size_t)NB * CC * MP];
__device__ __nv_bfloat16 g_Qh [(size_t)NB * CC * MP];    // Ht^2 [b][c][m]
__device__ __nv_bfloat16 g_Ql [(size_t)NB * CC * MP];
__device__ __nv_bfloat16 g_Sh[(size_t)NB * NP * MP];     // softmax probs
__device__ __nv_bfloat16 g_Sl[(size_t)NB * NP * MP];

// ============================================================================
// Kernel 1: 1x1 conv GEMM (FFMA2); epilogue emits bf16 hi/lo splits.
//   dest 0: F[n][k]   dest 1: G[m][k]   dest 2: Ht[c][m] + Ht^2[c][m]
// acc pairs: rows i,i+1 (r = 2*ii + 0/1), cols j,j+1 (per jj).
// ============================================================================
__global__ void __launch_bounds__(256)
conv1x1_gemm(const float* __restrict__ X, const float* __restrict__ W,
             const float* __restrict__ bias, int dest)
{
    const int I = NP, K = KPD, J = KPD;
    __shared__ __align__(16) float As[8 * 128];
    __shared__ __align__(16) float Bs[8 * 130];

    int b  = blockIdx.z;
    int i0 = blockIdx.x * 128;
    int j0 = blockIdx.y * 128;
    const float* Xb = X + (size_t)b * K * I;

    int tid = threadIdx.x;
    int tx = tid & 15, ty = tid >> 4;

    u64 acc[8][4];
#pragma unroll
    for (int r = 0; r < 8; r++)
#pragma unroll
        for (int j = 0; j < 4; j++) acc[r][j] = 0ull;

    for (int kk = 0; kk < K; kk += 8) {
#pragma unroll
        for (int p = 0; p < 4; p++) {
            int e = tid + p * 256;
            int i = e & 127, k = e >> 7;
            As[k * 128 + i] = Xb[(size_t)(kk + k) * I + i0 + i];
        }
#pragma unroll
        for (int p = 0; p < 4; p++) {
            int e = tid + p * 256;
            int k = e & 7, j = e >> 3;
            Bs[k * 130 + j] = W[(size_t)(j0 + j) * K + kk + k];
        }
        __syncthreads();
#pragma unroll
        for (int k = 0; k < 8; k++) {
            u64 ad[8], bp[4];
#pragma unroll
            for (int ii = 0; ii < 4; ii++) {
                float2 a = unpack2(ldp(&As[k * 128 + 2 * ty + 32 * ii]));
                ad[2 * ii]     = dup2(a.x);
                ad[2 * ii + 1] = dup2(a.y);
            }
#pragma unroll
            for (int jj = 0; jj < 4; jj++)
                bp[jj] = ldp(&Bs[k * 130 + 2 * tx + 32 * jj]);
#pragma unroll
            for (int r = 0; r < 8; r++)
#pragma unroll
                for (int jj = 0; jj < 4; jj++)
                    ffma2(acc[r][jj], ad[r], bp[jj]);
        }
        __syncthreads();
    }

    if (dest != 2) {
        size_t bb = (size_t)b * NP * KPD;   // F and G have same extents
        __nv_bfloat16* Dh = (dest == 0 ? g_Fh : g_Gh) + bb;
        __nv_bfloat16* Dl = (dest == 0 ? g_Fl : g_Gl) + bb;
#pragma unroll
        for (int r = 0; r < 8; r++) {
            int i = i0 + 2 * ty + 32 * (r >> 1) + (r & 1);
#pragma unroll
            for (int jj = 0; jj < 4; jj++) {
                int j = j0 + 2 * tx + 32 * jj;
                float2 v = unpack2(acc[r][jj]);
                float2 bv = *reinterpret_cast<const float2*>(&bias[j]);
                uint32_t lo;
                uint32_t hi = bpack2(v.x + bv.x, v.y + bv.y, lo);
                size_t idx = (size_t)i * J + j;   // j contiguous
                *reinterpret_cast<uint32_t*>(Dh + idx) = hi;
                *reinterpret_cast<uint32_t*>(Dl + idx) = lo;
            }
        }
    } else {
        size_t bb = (size_t)b * CC * MP;
#pragma unroll
        for (int ii = 0; ii < 4; ii++) {
            int i = i0 + 2 * ty + 32 * ii;      // m-pair (i, i+1)
#pragma unroll
            for (int jj = 0; jj < 4; jj++) {
                int j = j0 + 2 * tx + 32 * jj;  // channels j, j+1
                float2 v0 = unpack2(acc[2 * ii][jj]);     // row i
                float2 v1 = unpack2(acc[2 * ii + 1][jj]); // row i+1
                float2 bv = *reinterpret_cast<const float2*>(&bias[j]);
                float a0 = v0.x + bv.x, a1 = v1.x + bv.x; // chan j
                float c0 = v0.y + bv.y, c1 = v1.y + bv.y; // chan j+1
                size_t idx0 = bb + (size_t)j * MP + i;
                size_t idx1 = bb + (size_t)(j + 1) * MP + i;
                uint32_t lo, hi;
                hi = bpack2(a0, a1, lo);
                *reinterpret_cast<uint32_t*>(g_Hth + idx0) = hi;
                *reinterpret_cast<uint32_t*>(g_Htl + idx0) = lo;
                hi = bpack2(a0 * a0, a1 * a1, lo);
                *reinterpret_cast<uint32_t*>(g_Qh + idx0) = hi;
                *reinterpret_cast<uint32_t*>(g_Ql + idx0) = lo;
                hi = bpack2(c0, c1, lo);
                *reinterpret_cast<uint32_t*>(g_Hth + idx1) = hi;
                *reinterpret_cast<uint32_t*>(g_Htl + idx1) = lo;
                hi = bpack2(c0 * c0, c1 * c1, lo);
                *reinterpret_cast<uint32_t*>(g_Qh + idx1) = hi;
                *reinterpret_cast<uint32_t*>(g_Ql + idx1) = lo;
            }
        }
    }
}

// ============================================================================
// Kernel 2: logits GEMM via mma.sync bf16 (3-term split).
//   S[n][m] = sum_k F[n][k] * G[m][k]
// Block 128n x 128m, KC=32 over k, cp.async double-buffered.
// smem stage: Fh,Fl,Gh,Gl each 128 rows x 80B (64B data + 16B pad) = 10240B.
// ============================================================================
#define L_ARR  10240
#define L_STG  (4 * L_ARR)
#define L_SMEM (2 * L_STG)
#define L_STAGES (KPD / 32)   // 16

__device__ __forceinline__ void logits_issue(int s, uint32_t sb, int tid,
                                             int b, int n0, int m0)
{
    uint32_t base = sb + (uint32_t)(s & 1) * L_STG;
    int k0 = s * 32;
    size_t fb = (size_t)b * NP * KPD;
    size_t gb = (size_t)b * MP * KPD;
#pragma unroll
    for (int q = 0; q < 8; q++) {
        int id = q * 256 + tid;
        int arr = id >> 9, rem = id & 511, row = rem >> 2, c = rem & 3;
        const __nv_bfloat16* src;
        if (arr == 0)      src = g_Fh + fb + (size_t)(n0 + row) * KPD + k0 + c * 8;
        else if (arr == 1) src = g_Fl + fb + (size_t)(n0 + row) * KPD + k0 + c * 8;
        else if (arr == 2) src = g_Gh + gb + (size_t)(m0 + row) * KPD + k0 + c * 8;
        else               src = g_Gl + gb + (size_t)(m0 + row) * KPD + k0 + c * 8;
        uint32_t dst = base + (uint32_t)arr * L_ARR + row * 80 + c * 16;
        CP_ASYNC16(dst, (const void*)src);
    }
    CP_COMMIT();
}

__global__ void __launch_bounds__(256)
logits_hmma()
{
    extern __shared__ char sm[];
    uint32_t sb = smem_u32(sm);
    int tid = threadIdx.x, lane = tid & 31, warp = tid >> 5;
    int wn = warp >> 1, wm = warp & 1;     // 4 x 2 warp grid: 32n x 64m each
    int b = blockIdx.z, m0 = blockIdx.x * 128, n0 = blockIdx.y * 128;
    float* Sb = g_S + (size_t)b * NP * MP;

    float d[2][8][4];
#pragma unroll
    for (int a = 0; a < 2; a++)
#pragma unroll
        for (int j = 0; j < 8; j++)
#pragma unroll
            for (int r = 0; r < 4; r++) d[a][j][r] = 0.f;

    logits_issue(0, sb, tid, b, n0, m0);

    int r8 = lane & 7;
    for (int s = 0; s < L_STAGES; s++) {
        if (s + 1 < L_STAGES) { logits_issue(s + 1, sb, tid, b, n0, m0); CP_WAIT1(); }
        else                  { CP_WAIT0(); }
        __syncthreads();

        uint32_t base = sb + (uint32_t)(s & 1) * L_STG;
#pragma unroll
        for (int ks = 0; ks < 2; ks++) {
            // A fragments (F): rows = n, x4 covers 16n x 16k
            uint32_t Ah[2][4], Al[2][4];
            int arow = r8 + ((lane >> 3) & 1) * 8;
            int akb  = ks * 16 + ((lane >> 4) & 1) * 8;
#pragma unroll
            for (int nt = 0; nt < 2; nt++) {
                uint32_t aoff = (uint32_t)((wn * 32 + nt * 16 + arow) * 80 + akb * 2);
                LDM_X4(Ah[nt][0], Ah[nt][1], Ah[nt][2], Ah[nt][3], base + 0 * L_ARR + aoff);
                LDM_X4(Al[nt][0], Al[nt][1], Al[nt][2], Al[nt][3], base + 1 * L_ARR + aoff);
            }
            // B fragments (G): rows = m, x4 covers 16m x 16k
            int brow = r8 + ((lane >> 4) & 1) * 8;
            int bkb  = ks * 16 + ((lane >> 3) & 1) * 8;
#pragma unroll
            for (int mg = 0; mg < 4; mg++) {
                uint32_t boff = (uint32_t)((wm * 64 + mg * 16 + brow) * 80 + bkb * 2);
                uint32_t Bh[4], Bl[4];
                LDM_X4(Bh[0], Bh[1], Bh[2], Bh[3], base + 2 * L_ARR + boff);
                LDM_X4(Bl[0], Bl[1], Bl[2], Bl[3], base + 3 * L_ARR + boff);
#pragma unroll
                for (int nt = 0; nt < 2; nt++) {
                    float* p0 = d[nt][2 * mg];
                    float* p1 = d[nt][2 * mg + 1];
                    mma16816(p0, Ah[nt], Bh[0], Bh[1]);
                    mma16816(p0, Ah[nt], Bl[0], Bl[1]);
                    mma16816(p0, Al[nt], Bh[0], Bh[1]);
                    mma16816(p1, Ah[nt], Bh[2], Bh[3]);
                    mma16816(p1, Ah[nt], Bl[2], Bl[3]);
                    mma16816(p1, Al[nt], Bh[2], Bh[3]);
                }
            }
        }
        __syncthreads();
    }

    // Epilogue: f32 logits [n][m]
#pragma unroll
    for (int nt = 0; nt < 2; nt++)
#pragma unroll
        for (int m8 = 0; m8 < 8; m8++) {
            int n = n0 + wn * 32 + nt * 16 + (lane >> 2);
            int m = m0 + wm * 64 + m8 * 8 + (lane & 3) * 2;
            *reinterpret_cast<float2*>(&Sb[(size_t)n * MP + m]) =
                make_float2(d[nt][m8][0], d[nt][m8][1]);
            *reinterpret_cast<float2*>(&Sb[(size_t)(n + 8) * MP + m]) =
                make_float2(d[nt][m8][2], d[nt][m8][3]);
        }
}

// ============================================================================
// Kernel 3: row softmax; reads f32 logits, writes bf16 hi/lo probabilities.
// ============================================================================
__global__ void __launch_bounds__(256)
softmax_rows()
{
    __shared__ float red[256];
    int row = blockIdx.x;
    size_t base = (size_t)row * MP;
    int tid = threadIdx.x;

    float2 v[8];
    float lmax = -1e30f;
#pragma unroll
    for (int t = 0; t < 8; t++) {
        v[t] = *reinterpret_cast<const float2*>(&g_S[base + tid * 2 + t * 512]);
        lmax = fmaxf(lmax, fmaxf(v[t].x, v[t].y));
    }
    red[tid] = lmax;
    __syncthreads();
    for (int s = 128; s > 0; s >>= 1) {
        if (tid < s) red[tid] = fmaxf(red[tid], red[tid + s]);
        __syncthreads();
    }
    float m = red[0];
    __syncthreads();

    float lsum = 0.f;
#pragma unroll
    for (int t = 0; t < 8; t++) {
        v[t].x = __expf(v[t].x - m);
        v[t].y = __expf(v[t].y - m);
        lsum += v[t].x + v[t].y;
    }
    red[tid] = lsum;
    __syncthreads();
    for (int s = 128; s > 0; s >>= 1) {
        if (tid < s) red[tid] += red[tid + s];
        __syncthreads();
    }
    float inv = 1.f / red[0];

#pragma unroll
    for (int t = 0; t < 8; t++) {
        size_t idx = base + tid * 2 + t * 512;
        uint32_t lo;
        uint32_t hi = bpack2(v[t].x * inv, v[t].y * inv, lo);
        *reinterpret_cast<uint32_t*>(&g_Sh[idx]) = hi;
        *reinterpret_cast<uint32_t*>(&g_Sl[idx]) = lo;
    }
}

// ============================================================================
// Kernel 4: dual GEMM (mean & e2) via mma.sync bf16 + fused epilogue.
//   mean[c][n] = sum_m Ht[c][m] * S[n][m];  e2 with Ht^2.
// Block 128c x 128n, KC=32 over m. A = Ht/Q rows=c; B = S rows=n.
// smem stage: Hth,Htl,Qh,Ql,Sh,Sl each 128 x 80B = 10240B -> 61440B/stage.
// ============================================================================
#define M_ARR  10240
#define M_STG  (6 * M_ARR)
#define M_SMEM (2 * M_STG)
#define M_STAGES (MP / 32)   // 128

__device__ __forceinline__ void meanstd_issue(int s, uint32_t sb, int tid,
                                              int b, int cc0, int n0)
{
    uint32_t base = sb + (uint32_t)(s & 1) * M_STG;
    int mm = s * 32;
    size_t hb = (size_t)b * CC * MP;
    size_t pb = (size_t)b * NP * MP;
#pragma unroll
    for (int q = 0; q < 12; q++) {
        int id = q * 256 + tid;
        int arr = id >> 9, rem = id & 511, row = rem >> 2, c = rem & 3;
        const __nv_bfloat16* src;
        if (arr == 0)      src = g_Hth + hb + (size_t)(cc0 + row) * MP + mm + c * 8;
        else if (arr == 1) src = g_Htl + hb + (size_t)(cc0 + row) * MP + mm + c * 8;
        else if (arr == 2) src = g_Qh  + hb + (size_t)(cc0 + row) * MP + mm + c * 8;
        else if (arr == 3) src = g_Ql  + hb + (size_t)(cc0 + row) * MP + mm + c * 8;
        else if (arr == 4) src = g_Sh  + pb + (size_t)(n0 + row) * MP + mm + c * 8;
        else               src = g_Sl  + pb + (size_t)(n0 + row) * MP + mm + c * 8;
        uint32_t dst = base + (uint32_t)arr * M_ARR + row * 80 + c * 16;
        CP_ASYNC16(dst, (const void*)src);
    }
    CP_COMMIT();
}

__global__ void __launch_bounds__(256, 1)
meanstd_hmma(const float* __restrict__ c_x, float* __restrict__ out)
{
    extern __shared__ char sm[];
    uint32_t sb = smem_u32(sm);
    int tid = threadIdx.x, lane = tid & 31, warp = tid >> 5;
    int wc = warp >> 1, wn = warp & 1;     // 4 x 2 warp grid: 32c x 64n each
    int b = blockIdx.z, n0 = blockIdx.x * 128, cc0 = blockIdx.y * 128;

    float dm[2][8][4], de[2][8][4];
#pragma unroll
    for (int a = 0; a < 2; a++)
#pragma unroll
        for (int j = 0; j < 8; j++)
#pragma unroll
            for (int r = 0; r < 4; r++) { dm[a][j][r] = 0.f; de[a][j][r] = 0.f; }

    meanstd_issue(0, sb, tid, b, cc0, n0);

    int r8 = lane & 7;
    for (int s = 0; s < M_STAGES; s++) {
        if (s + 1 < M_STAGES) { meanstd_issue(s + 1, sb, tid, b, cc0, n0); CP_WAIT1(); }
        else                  { CP_WAIT0(); }
        __syncthreads();

        uint32_t base = sb + (uint32_t)(s & 1) * M_STG;
#pragma unroll
        for (int ks = 0; ks < 2; ks++) {
            uint32_t Hh[2][4], Hl[2][4], Wh[2][4], Wl[2][4];
            int arow = r8 + ((lane >> 3) & 1) * 8;
            int akb  = ks * 16 + ((lane >> 4) & 1) * 8;
#pragma unroll
            for (int ct = 0; ct < 2; ct++) {
                uint32_t aoff = (uint32_t)((wc * 32 + ct * 16 + arow) * 80 + akb * 2);
                LDM_X4(Hh[ct][0], Hh[ct][1], Hh[ct][2], Hh[ct][3], base + 0 * M_ARR + aoff);
                LDM_X4(Hl[ct][0], Hl[ct][1], Hl[ct][2], Hl[ct][3], base + 1 * M_ARR + aoff);
                LDM_X4(Wh[ct][0], Wh[ct][1], Wh[ct][2], Wh[ct][3], base + 2 * M_ARR + aoff);
                LDM_X4(Wl[ct][0], Wl[ct][1], Wl[ct][2], Wl[ct][3], base + 3 * M_ARR + aoff);
            }
            int brow = r8 + ((lane >> 4) & 1) * 8;
            int bkb  = ks * 16 + ((lane >> 3) & 1) * 8;
#pragma unroll
            for (int ng = 0; ng < 4; ng++) {
                uint32_t boff = (uint32_t)((wn * 64 + ng * 16 + brow) * 80 + bkb * 2);
                uint32_t Sh4[4], Sl4[4];
                LDM_X4(Sh4[0], Sh4[1], Sh4[2], Sh4[3], base + 4 * M_ARR + boff);
                LDM_X4(Sl4[0], Sl4[1], Sl4[2], Sl4[3], base + 5 * M_ARR + boff);
#pragma unroll
                for (int ct = 0; ct < 2; ct++) {
#pragma unroll
                    for (int sub = 0; sub < 2; sub++) {
                        uint32_t s0 = Sh4[2 * sub], s1 = Sh4[2 * sub + 1];
                        uint32_t t0 = Sl4[2 * sub], t1 = Sl4[2 * sub + 1];
                        float* pm = dm[ct][2 * ng + sub];
                        float* pe = de[ct][2 * ng + sub];
                        mma16816(pm, Hh[ct], s0, s1);
                        mma16816(pm, Hh[ct], t0, t1);
                        mma16816(pm, Hl[ct], s0, s1);
                        mma16816(pe, Wh[ct], s0, s1);
                        mma16816(pe, Wh[ct], t0, t1);
                        mma16816(pe, Wl[ct], s0, s1);
                    }
                }
            }
        }
        __syncthreads();
    }

    // Fused epilogue: out[b][c][n] = sqrt(relu(e2 - mean^2)) * c_x + mean
#pragma unroll
    for (int ct = 0; ct < 2; ct++)
#pragma unroll
        for (int j = 0; j < 8; j++) {
            int cbase = cc0 + wc * 32 + ct * 16 + (lane >> 2);
            int n = n0 + wn * 64 + j * 8 + (lane & 3) * 2;
#pragma unroll
            for (int rr = 0; rr < 2; rr++) {
                int cr = cbase + rr * 8;
                float m0v = dm[ct][j][2 * rr],     e0 = de[ct][j][2 * rr];
                float m1v = dm[ct][j][2 * rr + 1], e1 = de[ct][j][2 * rr + 1];
                size_t idx = ((size_t)b * CC + cr) * NP + n;
                float2 cx = *reinterpret_cast<const float2*>(&c_x[idx]);
                float sd0 = sqrtf(fmaxf(e0 - m0v * m0v, 0.f));
                float sd1 = sqrtf(fmaxf(e1 - m1v * m1v, 0.f));
                *reinterpret_cast<float2*>(&out[idx]) =
                    make_float2(sd0 * cx.x + m0v, sd1 * cx.y + m1v);
            }
        }
}

// ============================================================================
// Launch
// ============================================================================
extern "C" void kernel_launch(void* const* d_in, const int* in_sizes, int n_in,
                              void* d_out, int out_size)
{
    const float* c_x  = (const float*)d_in[0];
    const float* s_x  = (const float*)d_in[1];
    const float* c_1x = (const float*)d_in[2];
    const float* s_1x = (const float*)d_in[3];
    const float* f_w  = (const float*)d_in[4];
    const float* f_b  = (const float*)d_in[5];
    const float* g_w  = (const float*)d_in[6];
    const float* g_b  = (const float*)d_in[7];
    const float* h_w  = (const float*)d_in[8];
    const float* h_b  = (const float*)d_in[9];
    float* out = (float*)d_out;

    (void)in_sizes; (void)n_in; (void)out_size;

    static int attr_done = 0;
    if (!attr_done) {
        cudaFuncSetAttribute(logits_hmma,
                             cudaFuncAttributeMaxDynamicSharedMemorySize, L_SMEM);
        cudaFuncSetAttribute(meanstd_hmma,
                             cudaFuncAttributeMaxDynamicSharedMemorySize, M_SMEM);
        attr_done = 1;
    }

    dim3 gridA(NP / 128, KPD / 128, NB);               // (32, 4, 4)
    conv1x1_gemm<<<gridA, 256>>>(c_1x, f_w, f_b, 0);   // F  [n][k]
    conv1x1_gemm<<<gridA, 256>>>(s_1x, g_w, g_b, 1);   // G  [m][k]
    conv1x1_gemm<<<gridA, 256>>>(s_x,  h_w, h_b, 2);   // Ht [c][m] + Ht^2

    dim3 gridL(MP / 128, NP / 128, NB);                // (32, 32, 4)
    logits_hmma<<<gridL, 256, L_SMEM>>>();

    softmax_rows<<<NB * NP, 256>>>();                  // 16384 rows

    dim3 gridM(NP / 128, CC / 128, NB);                // (32, 4, 4)
    meanstd_hmma<<<gridM, 256, M_SMEM>>>(c_x, out);
}

// round 14
// speedup vs baseline: 2.9013x; 1.1518x over previous
#include <cuda_runtime.h>
#include <cuda_bf16.h>
#include <math.h>
#include <stdint.h>

// Problem constants
#define NB 4          // batch
#define CC 512        // channels C
#define KPD 512       // key planes
#define NP 4096       // H*W
#define MP 4096       // HS*WS

// ============================================================================
// bf16 split helpers
// ============================================================================
__device__ __forceinline__ uint32_t bpack2(float v0, float v1,
                                           uint32_t& lo_out) {
    __nv_bfloat16 h0 = __float2bfloat16(v0);
    __nv_bfloat16 h1 = __float2bfloat16(v1);
    __nv_bfloat16 l0 = __float2bfloat16(v0 - __bfloat162float(h0));
    __nv_bfloat16 l1 = __float2bfloat16(v1 - __bfloat162float(h1));
    uint16_t uh0 = *reinterpret_cast<uint16_t*>(&h0);
    uint16_t uh1 = *reinterpret_cast<uint16_t*>(&h1);
    uint16_t ul0 = *reinterpret_cast<uint16_t*>(&l0);
    uint16_t ul1 = *reinterpret_cast<uint16_t*>(&l1);
    lo_out = (uint32_t)ul0 | ((uint32_t)ul1 << 16);
    return (uint32_t)uh0 | ((uint32_t)uh1 << 16);
}

// ============================================================================
// HMMA / ldmatrix / cp.async (portable sm_80+ PTX — valid on plain sm_103)
// ============================================================================
__device__ __forceinline__ uint32_t smem_u32(const void* p) {
    uint32_t a;
    asm("{ .reg .u64 t; cvta.to.shared.u64 t, %1; cvt.u32.u64 %0, t; }"
        : "=r"(a) : "l"(p));
    return a;
}

#define LDM_X4(r0, r1, r2, r3, a) \
    asm volatile("ldmatrix.sync.aligned.m8n8.x4.shared.b16 {%0,%1,%2,%3}, [%4];" \
                 : "=r"(r0), "=r"(r1), "=r"(r2), "=r"(r3) : "r"(a))

__device__ __forceinline__ void mma16816(float* d, const uint32_t* a,
                                         uint32_t b0, uint32_t b1) {
    asm volatile(
        "mma.sync.aligned.m16n8k16.row.col.f32.bf16.bf16.f32 "
        "{%0,%1,%2,%3}, {%4,%5,%6,%7}, {%8,%9}, {%0,%1,%2,%3};"
        : "+f"(d[0]), "+f"(d[1]), "+f"(d[2]), "+f"(d[3])
        : "r"(a[0]), "r"(a[1]), "r"(a[2]), "r"(a[3]), "r"(b0), "r"(b1));
}

#define CP_ASYNC16(dst, src) \
    asm volatile("cp.async.cg.shared.global [%0], [%1], 16;" \
                 :: "r"(dst), "l"(src))
#define CP_COMMIT() asm volatile("cp.async.commit_group;" ::: "memory")
#define CP_WAIT0()  asm volatile("cp.async.wait_group 0;" ::: "memory")
#define CP_WAIT1()  asm volatile("cp.async.wait_group 1;" ::: "memory")

// ============================================================================
// Device-global scratch (alloc-free per harness rules)
// ============================================================================
__device__ float g_S[(size_t)NB * NP * MP];              // logits f32
__device__ __nv_bfloat16 g_Fh[(size_t)NB * NP * KPD];    // F [b][n][k] hi
__device__ __nv_bfloat16 g_Fl[(size_t)NB * NP * KPD];
__device__ __nv_bfloat16 g_Gh[(size_t)NB * MP * KPD];    // G [b][m][k]
__device__ __nv_bfloat16 g_Gl[(size_t)NB * MP * KPD];
__device__ __nv_bfloat16 g_Hth[(size_t)NB * CC * MP];    // Ht [b][c][m]
__device__ __nv_bfloat16 g_Htl[(size_t)NB * CC * MP];
__device__ __nv_bfloat16 g_Qh [(size_t)NB * CC * MP];    // Ht^2 [b][c][m]
__device__ __nv_bfloat16 g_Ql [(size_t)NB * CC * MP];
__device__ __nv_bfloat16 g_Sh[(size_t)NB * NP * MP];     // softmax probs
__device__ __nv_bfloat16 g_Sl[(size_t)NB * NP * MP];
// Conv staging (reused sequentially for c_1x, s_1x, s_x)
__device__ __nv_bfloat16 g_Xth[(size_t)NB * NP * KPD];   // X^T [b][i][k] hi
__device__ __nv_bfloat16 g_Xtl[(size_t)NB * NP * KPD];
__device__ __nv_bfloat16 g_Wh[(size_t)KPD * KPD];        // W [j][k] hi
__device__ __nv_bfloat16 g_Wl[(size_t)KPD * KPD];

// ============================================================================
// Split / transpose kernels
// ============================================================================
// X [b][K][I] f32 -> Xt hi/lo [b][I][K] bf16 (32x32 smem tiles)
__global__ void __launch_bounds__(256)
split_xt(const float* __restrict__ X)
{
    __shared__ float tile[32][33];
    int b = blockIdx.z;
    int i0 = blockIdx.x * 32, k0 = blockIdx.y * 32;
    int tx = threadIdx.x & 31, ty = threadIdx.x >> 5;   // ty 0..7
    const float* Xb = X + (size_t)b * KPD * NP;
#pragma unroll
    for (int r = 0; r < 4; r++) {
        int k = ty + r * 8;
        tile[k][tx] = Xb[(size_t)(k0 + k) * NP + i0 + tx];
    }
    __syncthreads();
    size_t ob = (size_t)b * NP * KPD;
#pragma unroll
    for (int r = 0; r < 4; r++) {
        int i = ty + r * 8;
        float v = tile[tx][i];
        __nv_bfloat16 h = __float2bfloat16(v);
        __nv_bfloat16 l = __float2bfloat16(v - __bfloat162float(h));
        size_t idx = ob + (size_t)(i0 + i) * KPD + k0 + tx;
        g_Xth[idx] = h;
        g_Xtl[idx] = l;
    }
}

// W [J][K] f32 -> Wh/Wl bf16, same layout
__global__ void __launch_bounds__(256)
split_wk(const float* __restrict__ W)
{
    int idx = blockIdx.x * 256 + threadIdx.x;   // each handles 2 floats
    float2 v = reinterpret_cast<const float2*>(W)[idx];
    uint32_t lo;
    uint32_t hi = bpack2(v.x, v.y, lo);
    reinterpret_cast<uint32_t*>(g_Wh)[idx] = hi;
    reinterpret_cast<uint32_t*>(g_Wl)[idx] = lo;
}

// ============================================================================
// Shared pipeline geometry: 4 smem arrays x 128 rows x 64B data (+16B pad)
// ============================================================================
#define P_ARR  10240
#define P_STG  (4 * P_ARR)
#define P_SMEM (2 * P_STG)

// ============================================================================
// Conv GEMM via HMMA (3-term split). stages = KPD/32 = 16.
//   conv_nk: Out[i][j] = sum_k Xt[i][k] W[j][k] + b[j]  -> F/G [n][k] split
//   conv_cm: Out[j][i] = sum_k W[j][k] Xt[i][k] + b[j]  -> Ht,Ht^2 [c][m]
// ============================================================================
#define C_STAGES (KPD / 32)

__device__ __forceinline__ void conv_issue(int s, uint32_t sb, int tid,
                                           size_t xb, int a0, int b0, int swap)
{
    uint32_t base = sb + (uint32_t)(s & 1) * P_STG;
    int k0 = s * 32;
#pragma unroll
    for (int q = 0; q < 8; q++) {
        int id = q * 256 + tid;
        int arr = id >> 9, rem = id & 511, row = rem >> 2, c = rem & 3;
        const __nv_bfloat16* src;
        if (!swap) {   // A = Xt rows a0, B = W rows b0
            if (arr == 0)      src = g_Xth + xb + (size_t)(a0 + row) * KPD + k0 + c * 8;
            else if (arr == 1) src = g_Xtl + xb + (size_t)(a0 + row) * KPD + k0 + c * 8;
            else if (arr == 2) src = g_Wh + (size_t)(b0 + row) * KPD + k0 + c * 8;
            else               src = g_Wl + (size_t)(b0 + row) * KPD + k0 + c * 8;
        } else {       // A = W rows a0, B = Xt rows b0
            if (arr == 0)      src = g_Wh + (size_t)(a0 + row) * KPD + k0 + c * 8;
            else if (arr == 1) src = g_Wl + (size_t)(a0 + row) * KPD + k0 + c * 8;
            else if (arr == 2) src = g_Xth + xb + (size_t)(b0 + row) * KPD + k0 + c * 8;
            else               src = g_Xtl + xb + (size_t)(b0 + row) * KPD + k0 + c * 8;
        }
        uint32_t dst = base + (uint32_t)arr * P_ARR + row * 80 + c * 16;
        CP_ASYNC16(dst, (const void*)src);
    }
    CP_COMMIT();
}

// Core 128x128 3-term mainloop; accumulators d[2][8][4]; A rows warp wn (4), B
// cols warp wm (2). Identical fragment mapping to the validated logits kernel.
__device__ __forceinline__ void hmma_mainloop_stage(uint32_t base, int lane,
                                                    int wn, int wm,
                                                    float d[2][8][4])
{
    int r8 = lane & 7;
#pragma unroll
    for (int ks = 0; ks < 2; ks++) {
        uint32_t Ah[2][4], Al[2][4];
        int arow = r8 + ((lane >> 3) & 1) * 8;
        int akb  = ks * 16 + ((lane >> 4) & 1) * 8;
#pragma unroll
        for (int nt = 0; nt < 2; nt++) {
            uint32_t aoff = (uint32_t)((wn * 32 + nt * 16 + arow) * 80 + akb * 2);
            LDM_X4(Ah[nt][0], Ah[nt][1], Ah[nt][2], Ah[nt][3], base + 0 * P_ARR + aoff);
            LDM_X4(Al[nt][0], Al[nt][1], Al[nt][2], Al[nt][3], base + 1 * P_ARR + aoff);
        }
        int brow = r8 + ((lane >> 4) & 1) * 8;
        int bkb  = ks * 16 + ((lane >> 3) & 1) * 8;
#pragma unroll
        for (int mg = 0; mg < 4; mg++) {
            uint32_t boff = (uint32_t)((wm * 64 + mg * 16 + brow) * 80 + bkb * 2);
            uint32_t Bh[4], Bl[4];
            LDM_X4(Bh[0], Bh[1], Bh[2], Bh[3], base + 2 * P_ARR + boff);
            LDM_X4(Bl[0], Bl[1], Bl[2], Bl[3], base + 3 * P_ARR + boff);
#pragma unroll
            for (int nt = 0; nt < 2; nt++) {
                float* p0 = d[nt][2 * mg];
                float* p1 = d[nt][2 * mg + 1];
                mma16816(p0, Ah[nt], Bh[0], Bh[1]);
                mma16816(p0, Ah[nt], Bl[0], Bl[1]);
                mma16816(p0, Al[nt], Bh[0], Bh[1]);
                mma16816(p1, Ah[nt], Bh[2], Bh[3]);
                mma16816(p1, Ah[nt], Bl[2], Bl[3]);
                mma16816(p1, Al[nt], Bh[2], Bh[3]);
            }
        }
    }
}

// dest 0 -> F, 1 -> G: output [n][k] split, bias over columns
__global__ void __launch_bounds__(256)
conv_nk(const float* __restrict__ bias, int dest)
{
    extern __shared__ char sm[];
    uint32_t sb = smem_u32(sm);
    int tid = threadIdx.x, lane = tid & 31, warp = tid >> 5;
    int wn = warp >> 1, wm = warp & 1;
    int b = blockIdx.z, i0 = blockIdx.x * 128, j0 = blockIdx.y * 128;
    size_t xb = (size_t)b * NP * KPD;

    float d[2][8][4];
#pragma unroll
    for (int a = 0; a < 2; a++)
#pragma unroll
        for (int j = 0; j < 8; j++)
#pragma unroll
            for (int r = 0; r < 4; r++) d[a][j][r] = 0.f;

    conv_issue(0, sb, tid, xb, i0, j0, 0);
    for (int s = 0; s < C_STAGES; s++) {
        if (s + 1 < C_STAGES) { conv_issue(s + 1, sb, tid, xb, i0, j0, 0); CP_WAIT1(); }
        else                  { CP_WAIT0(); }
        __syncthreads();
        hmma_mainloop_stage(sb + (uint32_t)(s & 1) * P_STG, lane, wn, wm, d);
        __syncthreads();
    }

    size_t bb = (size_t)b * NP * KPD;
    __nv_bfloat16* Dh = (dest == 0 ? g_Fh : g_Gh) + bb;
    __nv_bfloat16* Dl = (dest == 0 ? g_Fl : g_Gl) + bb;
#pragma unroll
    for (int nt = 0; nt < 2; nt++)
#pragma unroll
        for (int m8 = 0; m8 < 8; m8++) {
            int n = i0 + wn * 32 + nt * 16 + (lane >> 2);
            int j = j0 + wm * 64 + m8 * 8 + (lane & 3) * 2;
            float2 bv = *reinterpret_cast<const float2*>(&bias[j]);
            uint32_t lo, hi;
            hi = bpack2(d[nt][m8][0] + bv.x, d[nt][m8][1] + bv.y, lo);
            *reinterpret_cast<uint32_t*>(Dh + (size_t)n * KPD + j) = hi;
            *reinterpret_cast<uint32_t*>(Dl + (size_t)n * KPD + j) = lo;
            hi = bpack2(d[nt][m8][2] + bv.x, d[nt][m8][3] + bv.y, lo);
            *reinterpret_cast<uint32_t*>(Dh + (size_t)(n + 8) * KPD + j) = hi;
            *reinterpret_cast<uint32_t*>(Dl + (size_t)(n + 8) * KPD + j) = lo;
        }
}

// Ht conv: output rows = channels -> Ht [c][m] and Ht^2 [c][m] splits
__global__ void __launch_bounds__(256)
conv_cm(const float* __restrict__ bias)
{
    extern __shared__ char sm[];
    uint32_t sb = smem_u32(sm);
    int tid = threadIdx.x, lane = tid & 31, warp = tid >> 5;
    int wc = warp >> 1, wm = warp & 1;
    int b = blockIdx.z, m0 = blockIdx.x * 128, c0 = blockIdx.y * 128;
    size_t xb = (size_t)b * NP * KPD;

    float d[2][8][4];
#pragma unroll
    for (int a = 0; a < 2; a++)
#pragma unroll
        for (int j = 0; j < 8; j++)
#pragma unroll
            for (int r = 0; r < 4; r++) d[a][j][r] = 0.f;

    conv_issue(0, sb, tid, xb, c0, m0, 1);
    for (int s = 0; s < C_STAGES; s++) {
        if (s + 1 < C_STAGES) { conv_issue(s + 1, sb, tid, xb, c0, m0, 1); CP_WAIT1(); }
        else                  { CP_WAIT0(); }
        __syncthreads();
        hmma_mainloop_stage(sb + (uint32_t)(s & 1) * P_STG, lane, wc, wm, d);
        __syncthreads();
    }

    size_t bb = (size_t)b * CC * MP;
#pragma unroll
    for (int ct = 0; ct < 2; ct++)
#pragma unroll
        for (int m8 = 0; m8 < 8; m8++) {
            int c = c0 + wc * 32 + ct * 16 + (lane >> 2);
            int m = m0 + wm * 64 + m8 * 8 + (lane & 3) * 2;
            float b0v = bias[c], b1v = bias[c + 8];
            float v0 = d[ct][m8][0] + b0v, v1 = d[ct][m8][1] + b0v;
            float v2 = d[ct][m8][2] + b1v, v3 = d[ct][m8][3] + b1v;
            size_t idx0 = bb + (size_t)c * MP + m;
            size_t idx1 = bb + (size_t)(c + 8) * MP + m;
            uint32_t lo, hi;
            hi = bpack2(v0, v1, lo);
            *reinterpret_cast<uint32_t*>(g_Hth + idx0) = hi;
            *reinterpret_cast<uint32_t*>(g_Htl + idx0) = lo;
            hi = bpack2(v0 * v0, v1 * v1, lo);
            *reinterpret_cast<uint32_t*>(g_Qh + idx0) = hi;
            *reinterpret_cast<uint32_t*>(g_Ql + idx0) = lo;
            hi = bpack2(v2, v3, lo);
            *reinterpret_cast<uint32_t*>(g_Hth + idx1) = hi;
            *reinterpret_cast<uint32_t*>(g_Htl + idx1) = lo;
            hi = bpack2(v2 * v2, v3 * v3, lo);
            *reinterpret_cast<uint32_t*>(g_Qh + idx1) = hi;
            *reinterpret_cast<uint32_t*>(g_Ql + idx1) = lo;
        }
}

// ============================================================================
// Kernel: logits GEMM via mma.sync bf16 (3-term split).
//   S[n][m] = sum_k F[n][k] * G[m][k];  KC=32, double-buffered.
// ============================================================================
#define L_STAGES (KPD / 32)   // 16

__device__ __forceinline__ void logits_issue(int s, uint32_t sb, int tid,
                                             int b, int n0, int m0)
{
    uint32_t base = sb + (uint32_t)(s & 1) * P_STG;
    int k0 = s * 32;
    size_t fb = (size_t)b * NP * KPD;
    size_t gb = (size_t)b * MP * KPD;
#pragma unroll
    for (int q = 0; q < 8; q++) {
        int id = q * 256 + tid;
        int arr = id >> 9, rem = id & 511, row = rem >> 2, c = rem & 3;
        const __nv_bfloat16* src;
        if (arr == 0)      src = g_Fh + fb + (size_t)(n0 + row) * KPD + k0 + c * 8;
        else if (arr == 1) src = g_Fl + fb + (size_t)(n0 + row) * KPD + k0 + c * 8;
        else if (arr == 2) src = g_Gh + gb + (size_t)(m0 + row) * KPD + k0 + c * 8;
        else               src = g_Gl + gb + (size_t)(m0 + row) * KPD + k0 + c * 8;
        uint32_t dst = base + (uint32_t)arr * P_ARR + row * 80 + c * 16;
        CP_ASYNC16(dst, (const void*)src);
    }
    CP_COMMIT();
}

__global__ void __launch_bounds__(256)
logits_hmma()
{
    extern __shared__ char sm[];
    uint32_t sb = smem_u32(sm);
    int tid = threadIdx.x, lane = tid & 31, warp = tid >> 5;
    int wn = warp >> 1, wm = warp & 1;
    int b = blockIdx.z, m0 = blockIdx.x * 128, n0 = blockIdx.y * 128;
    float* Sb = g_S + (size_t)b * NP * MP;

    float d[2][8][4];
#pragma unroll
    for (int a = 0; a < 2; a++)
#pragma unroll
        for (int j = 0; j < 8; j++)
#pragma unroll
            for (int r = 0; r < 4; r++) d[a][j][r] = 0.f;

    logits_issue(0, sb, tid, b, n0, m0);
    for (int s = 0; s < L_STAGES; s++) {
        if (s + 1 < L_STAGES) { logits_issue(s + 1, sb, tid, b, n0, m0); CP_WAIT1(); }
        else                  { CP_WAIT0(); }
        __syncthreads();
        hmma_mainloop_stage(sb + (uint32_t)(s & 1) * P_STG, lane, wn, wm, d);
        __syncthreads();
    }

#pragma unroll
    for (int nt = 0; nt < 2; nt++)
#pragma unroll
        for (int m8 = 0; m8 < 8; m8++) {
            int n = n0 + wn * 32 + nt * 16 + (lane >> 2);
            int m = m0 + wm * 64 + m8 * 8 + (lane & 3) * 2;
            *reinterpret_cast<float2*>(&Sb[(size_t)n * MP + m]) =
                make_float2(d[nt][m8][0], d[nt][m8][1]);
            *reinterpret_cast<float2*>(&Sb[(size_t)(n + 8) * MP + m]) =
                make_float2(d[nt][m8][2], d[nt][m8][3]);
        }
}

// ============================================================================
// Kernel: row softmax; reads f32 logits, writes bf16 hi/lo probabilities.
// ============================================================================
__global__ void __launch_bounds__(256)
softmax_rows()
{
    __shared__ float red[256];
    int row = blockIdx.x;
    size_t base = (size_t)row * MP;
    int tid = threadIdx.x;

    float2 v[8];
    float lmax = -1e30f;
#pragma unroll
    for (int t = 0; t < 8; t++) {
        v[t] = *reinterpret_cast<const float2*>(&g_S[base + tid * 2 + t * 512]);
        lmax = fmaxf(lmax, fmaxf(v[t].x, v[t].y));
    }
    red[tid] = lmax;
    __syncthreads();
    for (int s = 128; s > 0; s >>= 1) {
        if (tid < s) red[tid] = fmaxf(red[tid], red[tid + s]);
        __syncthreads();
    }
    float m = red[0];
    __syncthreads();

    float lsum = 0.f;
#pragma unroll
    for (int t = 0; t < 8; t++) {
        v[t].x = __expf(v[t].x - m);
        v[t].y = __expf(v[t].y - m);
        lsum += v[t].x + v[t].y;
    }
    red[tid] = lsum;
    __syncthreads();
    for (int s = 128; s > 0; s >>= 1) {
        if (tid < s) red[tid] += red[tid + s];
        __syncthreads();
    }
    float inv = 1.f / red[0];

#pragma unroll
    for (int t = 0; t < 8; t++) {
        size_t idx = base + tid * 2 + t * 512;
        uint32_t lo;
        uint32_t hi = bpack2(v[t].x * inv, v[t].y * inv, lo);
        *reinterpret_cast<uint32_t*>(&g_Sh[idx]) = hi;
        *reinterpret_cast<uint32_t*>(&g_Sl[idx]) = lo;
    }
}

// ============================================================================
// Kernel: dual GEMM (mean & e2) via mma.sync bf16 + fused epilogue.
//   mean[c][n] = sum_m Ht[c][m] * S[n][m];  e2 with Ht^2.
// Block 128c x 128n, KC=32; 6 smem arrays.
// ============================================================================
#define M_ARR  10240
#define M_STG  (6 * M_ARR)
#define M_SMEM (2 * M_STG)
#define M_STAGES (MP / 32)   // 128

__device__ __forceinline__ void meanstd_issue(int s, uint32_t sb, int tid,
                                              int b, int cc0, int n0)
{
    uint32_t base = sb + (uint32_t)(s & 1) * M_STG;
    int mm = s * 32;
    size_t hb = (size_t)b * CC * MP;
    size_t pb = (size_t)b * NP * MP;
#pragma unroll
    for (int q = 0; q < 12; q++) {
        int id = q * 256 + tid;
        int arr = id >> 9, rem = id & 511, row = rem >> 2, c = rem & 3;
        const __nv_bfloat16* src;
        if (arr == 0)      src = g_Hth + hb + (size_t)(cc0 + row) * MP + mm + c * 8;
        else if (arr == 1) src = g_Htl + hb + (size_t)(cc0 + row) * MP + mm + c * 8;
        else if (arr == 2) src = g_Qh  + hb + (size_t)(cc0 + row) * MP + mm + c * 8;
        else if (arr == 3) src = g_Ql  + hb + (size_t)(cc0 + row) * MP + mm + c * 8;
        else if (arr == 4) src = g_Sh  + pb + (size_t)(n0 + row) * MP + mm + c * 8;
        else               src = g_Sl  + pb + (size_t)(n0 + row) * MP + mm + c * 8;
        uint32_t dst = base + (uint32_t)arr * M_ARR + row * 80 + c * 16;
        CP_ASYNC16(dst, (const void*)src);
    }
    CP_COMMIT();
}

__global__ void __launch_bounds__(256, 1)
meanstd_hmma(const float* __restrict__ c_x, float* __restrict__ out)
{
    extern __shared__ char sm[];
    uint32_t sb = smem_u32(sm);
    int tid = threadIdx.x, lane = tid & 31, warp = tid >> 5;
    int wc = warp >> 1, wn = warp & 1;
    int b = blockIdx.z, n0 = blockIdx.x * 128, cc0 = blockIdx.y * 128;

    float dm[2][8][4], de[2][8][4];
#pragma unroll
    for (int a = 0; a < 2; a++)
#pragma unroll
        for (int j = 0; j < 8; j++)
#pragma unroll
            for (int r = 0; r < 4; r++) { dm[a][j][r] = 0.f; de[a][j][r] = 0.f; }

    meanstd_issue(0, sb, tid, b, cc0, n0);

    int r8 = lane & 7;
    for (int s = 0; s < M_STAGES; s++) {
        if (s + 1 < M_STAGES) { meanstd_issue(s + 1, sb, tid, b, cc0, n0); CP_WAIT1(); }
        else                  { CP_WAIT0(); }
        __syncthreads();

        uint32_t base = sb + (uint32_t)(s & 1) * M_STG;
#pragma unroll
        for (int ks = 0; ks < 2; ks++) {
            uint32_t Hh[2][4], Hl[2][4], Wh[2][4], Wl[2][4];
            int arow = r8 + ((lane >> 3) & 1) * 8;
            int akb  = ks * 16 + ((lane >> 4) & 1) * 8;
#pragma unroll
            for (int ct = 0; ct < 2; ct++) {
                uint32_t aoff = (uint32_t)((wc * 32 + ct * 16 + arow) * 80 + akb * 2);
                LDM_X4(Hh[ct][0], Hh[ct][1], Hh[ct][2], Hh[ct][3], base + 0 * M_ARR + aoff);
                LDM_X4(Hl[ct][0], Hl[ct][1], Hl[ct][2], Hl[ct][3], base + 1 * M_ARR + aoff);
                LDM_X4(Wh[ct][0], Wh[ct][1], Wh[ct][2], Wh[ct][3], base + 2 * M_ARR + aoff);
                LDM_X4(Wl[ct][0], Wl[ct][1], Wl[ct][2], Wl[ct][3], base + 3 * M_ARR + aoff);
            }
            int brow = r8 + ((lane >> 4) & 1) * 8;
            int bkb  = ks * 16 + ((lane >> 3) & 1) * 8;
#pragma unroll
            for (int ng = 0; ng < 4; ng++) {
                uint32_t boff = (uint32_t)((wn * 64 + ng * 16 + brow) * 80 + bkb * 2);
                uint32_t Sh4[4], Sl4[4];
                LDM_X4(Sh4[0], Sh4[1], Sh4[2], Sh4[3], base + 4 * M_ARR + boff);
                LDM_X4(Sl4[0], Sl4[1], Sl4[2], Sl4[3], base + 5 * M_ARR + boff);
#pragma unroll
                for (int ct = 0; ct < 2; ct++) {
#pragma unroll
                    for (int sub = 0; sub < 2; sub++) {
                        uint32_t s0 = Sh4[2 * sub], s1 = Sh4[2 * sub + 1];
                        uint32_t t0 = Sl4[2 * sub], t1 = Sl4[2 * sub + 1];
                        float* pm = dm[ct][2 * ng + sub];
                        float* pe = de[ct][2 * ng + sub];
                        mma16816(pm, Hh[ct], s0, s1);
                        mma16816(pm, Hh[ct], t0, t1);
                        mma16816(pm, Hl[ct], s0, s1);
                        mma16816(pe, Wh[ct], s0, s1);
                        mma16816(pe, Wh[ct], t0, t1);
                        mma16816(pe, Wl[ct], s0, s1);
                    }
                }
            }
        }
        __syncthreads();
    }

    // Fused epilogue: out[b][c][n] = sqrt(relu(e2 - mean^2)) * c_x + mean
#pragma unroll
    for (int ct = 0; ct < 2; ct++)
#pragma unroll
        for (int j = 0; j < 8; j++) {
            int cbase = cc0 + wc * 32 + ct * 16 + (lane >> 2);
            int n = n0 + wn * 64 + j * 8 + (lane & 3) * 2;
#pragma unroll
            for (int rr = 0; rr < 2; rr++) {
                int cr = cbase + rr * 8;
                float m0v = dm[ct][j][2 * rr],     e0 = de[ct][j][2 * rr];
                float m1v = dm[ct][j][2 * rr + 1], e1 = de[ct][j][2 * rr + 1];
                size_t idx = ((size_t)b * CC + cr) * NP + n;
                float2 cx = *reinterpret_cast<const float2*>(&c_x[idx]);
                float sd0 = sqrtf(fmaxf(e0 - m0v * m0v, 0.f));
                float sd1 = sqrtf(fmaxf(e1 - m1v * m1v, 0.f));
                *reinterpret_cast<float2*>(&out[idx]) =
                    make_float2(sd0 * cx.x + m0v, sd1 * cx.y + m1v);
            }
        }
}

// ============================================================================
// Launch
// ============================================================================
extern "C" void kernel_launch(void* const* d_in, const int* in_sizes, int n_in,
                              void* d_out, int out_size)
{
    const float* c_x  = (const float*)d_in[0];
    const float* s_x  = (const float*)d_in[1];
    const float* c_1x = (const float*)d_in[2];
    const float* s_1x = (const float*)d_in[3];
    const float* f_w  = (const float*)d_in[4];
    const float* f_b  = (const float*)d_in[5];
    const float* g_w  = (const float*)d_in[6];
    const float* g_b  = (const float*)d_in[7];
    const float* h_w  = (const float*)d_in[8];
    const float* h_b  = (const float*)d_in[9];
    float* out = (float*)d_out;

    (void)in_sizes; (void)n_in; (void)out_size;

    static int attr_done = 0;
    if (!attr_done) {
        cudaFuncSetAttribute(conv_nk,
                             cudaFuncAttributeMaxDynamicSharedMemorySize, P_SMEM);
        cudaFuncSetAttribute(conv_cm,
                             cudaFuncAttributeMaxDynamicSharedMemorySize, P_SMEM);
        cudaFuncSetAttribute(logits_hmma,
                             cudaFuncAttributeMaxDynamicSharedMemorySize, P_SMEM);
        cudaFuncSetAttribute(meanstd_hmma,
                             cudaFuncAttributeMaxDynamicSharedMemorySize, M_SMEM);
        attr_done = 1;
    }

    dim3 gridT(NP / 32, KPD / 32, NB);     // split_xt: (128, 16, 4)
    dim3 gridC(NP / 128, KPD / 128, NB);   // convs: (32, 4, 4)

    // F = f(c_1x)
    split_wk<<<512, 256>>>(f_w);
    split_xt<<<gridT, 256>>>(c_1x);
    conv_nk<<<gridC, 256, P_SMEM>>>(f_b, 0);

    // G = g(s_1x)
    split_wk<<<512, 256>>>(g_w);
    split_xt<<<gridT, 256>>>(s_1x);
    conv_nk<<<gridC, 256, P_SMEM>>>(g_b, 1);

    // Ht (+ Ht^2) = h(s_x), transposed output
    split_wk<<<512, 256>>>(h_w);
    split_xt<<<gridT, 256>>>(s_x);
    conv_cm<<<gridC, 256, P_SMEM>>>(h_b);

    dim3 gridL(MP / 128, NP / 128, NB);    // (32, 32, 4)
    logits_hmma<<<gridL, 256, P_SMEM>>>();

    softmax_rows<<<NB * NP, 256>>>();      // 16384 rows

    dim3 gridM(NP / 128, CC / 128, NB);    // (32, 4, 4)
    meanstd_hmma<<<gridM, 256, M_SMEM>>>(c_x, out);
}